// round 12
// baseline (speedup 1.0000x reference)
#include <cuda_runtime.h>
#include <math.h>
#include <stdint.h>

#define Tdim 4096
#define Hdim 4096
#define Idim 11008
#define NW ((size_t)Idim*(size_t)Hdim)
#define NCH_H 32            // Hdim/128
#define NCH_I 86            // Idim/128

// ---- static device scratch: transposed chunk blobs, 16KB per (tile, chunk) ----
// blob = [kw 0..31][128 words]: word (kw, col) at kw*512 + col*4
__device__ __align__(16) signed char g_wqg[NW];
__device__ __align__(16) signed char g_wqu[NW];
__device__ __align__(16) signed char g_wqd[NW];
__device__ __align__(16) signed char g_xqt[(size_t)Tdim*Hdim];
__device__ __align__(16) signed char g_hqt[(size_t)Tdim*Idim];
__device__ float g_gbuf[(size_t)Tdim*Idim];
__device__ float g_ainv[Tdim];
__device__ float g_hinv[Tdim];
__device__ float g_partial[3][2048];
__device__ float g_wscale[3];
__device__ float g_winv[3];
__device__ unsigned g_cnt = 0;

// ======================= PTX helpers =======================
__device__ __forceinline__ uint32_t smem_u32(const void* p) {
    uint32_t a;
    asm("{ .reg .u64 t; cvta.to.shared.u64 t, %1; cvt.u32.u64 %0, t; }" : "=r"(a) : "l"(p));
    return a;
}
#define MBAR_INIT(a, c) asm volatile("mbarrier.init.shared.b64 [%0], %1;" :: "r"(a), "r"(c) : "memory")
#define MBAR_EXPECT(a, b) asm volatile("mbarrier.arrive.expect_tx.shared.b64 _, [%0], %1;" :: "r"(a), "r"(b) : "memory")
__device__ __forceinline__ void mbar_wait(uint32_t addr, uint32_t parity) {
    asm volatile(
        "{\n\t.reg .pred P;\n\t"
        "LW_%=:\n\t"
        "mbarrier.try_wait.parity.acquire.cta.shared::cta.b64 P, [%0], %1, 0x989680;\n\t"
        "@P bra.uni LD_%=;\n\t"
        "bra.uni LW_%=;\n\t"
        "LD_%=:\n\t}"
        :: "r"(addr), "r"(parity) : "memory");
}
__device__ __forceinline__ void bulk_g2s(uint32_t dst, const void* src, uint32_t bytes, uint32_t mbar) {
    asm volatile("cp.async.bulk.shared::cluster.global.mbarrier::complete_tx::bytes [%0], [%1], %2, [%3];"
        :: "r"(dst), "l"(src), "r"(bytes), "r"(mbar) : "memory");
}

__device__ __forceinline__ int quant_word(float4 v, float sc, float lo, float hi) {
    int b0 = (int)fminf(hi, fmaxf(lo, rintf(v.x * sc)));
    int b1 = (int)fminf(hi, fmaxf(lo, rintf(v.y * sc)));
    int b2 = (int)fminf(hi, fmaxf(lo, rintf(v.z * sc)));
    int b3 = (int)fminf(hi, fmaxf(lo, rintf(v.w * sc)));
    return (b0 & 0xFF) | ((b1 & 0xFF) << 8) | ((b2 & 0xFF) << 16) | (b3 << 24);
}

// ======================= absmean + finalize =======================
__global__ void absmean_all(const float* __restrict__ wg, const float* __restrict__ wu,
                            const float* __restrict__ wd, long n) {
    __shared__ float red[256];
    __shared__ double redd[256];
    __shared__ bool amLast;
    int which = blockIdx.y;
    const float* w = which == 0 ? wg : (which == 1 ? wu : wd);
    float s = 0.f;
    long stride = (long)gridDim.x * blockDim.x;
    for (long i = (long)blockIdx.x * blockDim.x + threadIdx.x; i < n; i += stride)
        s += fabsf(w[i]);
    red[threadIdx.x] = s;
    __syncthreads();
    for (int o = 128; o > 0; o >>= 1) {
        if (threadIdx.x < o) red[threadIdx.x] += red[threadIdx.x + o];
        __syncthreads();
    }
    if (threadIdx.x == 0) {
        g_partial[which][blockIdx.x] = red[0];
        __threadfence();
        unsigned t = atomicAdd(&g_cnt, 1u);
        amLast = (t == gridDim.x * 3 - 1);
    }
    __syncthreads();
    if (amLast) {
        for (int m = 0; m < 3; m++) {
            double s2 = 0.0;
            for (int i = threadIdx.x; i < 2048; i += 256) s2 += (double)g_partial[m][i];
            redd[threadIdx.x] = s2;
            __syncthreads();
            for (int o = 128; o > 0; o >>= 1) {
                if (threadIdx.x < o) redd[threadIdx.x] += redd[threadIdx.x + o];
                __syncthreads();
            }
            if (threadIdx.x == 0) {
                float mean = (float)(redd[0] / (double)n);
                float cm = fmaxf(mean, 1e-5f);
                g_wscale[m] = 1.f / cm;
                g_winv[m] = cm;
            }
            __syncthreads();
        }
        if (threadIdx.x == 0) g_cnt = 0;
    }
}

// ======================= weight quant -> transposed blobs =======================
__global__ void quant_weight_all(const float* __restrict__ wg, const float* __restrict__ wu,
                                 const float* __restrict__ wd) {
    __shared__ int s[32][132];
    int which = blockIdx.y;
    const float* w; signed char* outb; int Kf, ktc;
    if (which == 0)      { w = wg; outb = g_wqg; Kf = Hdim; ktc = NCH_H; }
    else if (which == 1) { w = wu; outb = g_wqu; Kf = Hdim; ktc = NCH_H; }
    else                 { w = wd; outb = g_wqd; Kf = Idim; ktc = NCH_I; }
    int bx = blockIdx.x;
    int kc = bx % ktc, ntile = bx / ktc;
    int kc0 = kc * 128, n0 = ntile * 128;
    float sw = g_wscale[which];
    int t = threadIdx.x;
    int r = t >> 1, h = t & 1;
    const float* wr = w + (size_t)(n0 + r) * Kf + kc0 + h * 64;
    signed char* blob = outb + (((size_t)ntile * ktc + kc) << 14);
#pragma unroll
    for (int q = 0; q < 16; q++)
        s[h * 16 + q][r] = quant_word(*(const float4*)(wr + q * 4), sw, -1.f, 1.f);
    __syncthreads();
    int kw = t >> 3, seg = t & 7;
    signed char* dst = blob + kw * 512 + seg * 64;
#pragma unroll
    for (int q = 0; q < 16; q += 4)
        *(int4*)(dst + q * 4) = make_int4(s[kw][seg*16+q], s[kw][seg*16+q+1],
                                          s[kw][seg*16+q+2], s[kw][seg*16+q+3]);
}

// ======================= act quant -> transposed blobs =======================
__global__ void quant_act_t(const float* __restrict__ x, signed char* __restrict__ xqt,
                            float* __restrict__ ainv, int Kf, int nch) {
    __shared__ float rscale[32];
    __shared__ float rinvs[32];
    __shared__ int s[32][33];
    int t = threadIdx.x, warp = t >> 5, lane = t & 31;
    int row0 = blockIdx.x * 32;
    int mt = row0 >> 7, rbase = row0 & 127;
#pragma unroll
    for (int rr = 0; rr < 4; rr++) {
        int r = warp * 4 + rr;
        const float4* xr = (const float4*)(x + (size_t)(row0 + r) * Kf);
        float mx = 0.f;
        for (int i = lane; i < Kf / 4; i += 32) {
            float4 v = xr[i];
            mx = fmaxf(mx, fmaxf(fmaxf(fabsf(v.x), fabsf(v.y)), fmaxf(fabsf(v.z), fabsf(v.w))));
        }
#pragma unroll
        for (int o = 16; o > 0; o >>= 1) mx = fmaxf(mx, __shfl_xor_sync(0xFFFFFFFFu, mx, o));
        if (lane == 0) {
            float cm = fmaxf(mx, 1e-5f);
            rscale[r] = 127.f / cm;
            rinvs[r] = cm * (1.f / 127.f);
        }
    }
    __syncthreads();
    if (t < 32) ainv[row0 + t] = rinvs[t];
    int r = t >> 3, seg = t & 7;
    float sc = rscale[r];
    const float* xr = x + (size_t)(row0 + r) * Kf;
    for (int kt = 0; kt < nch; kt++) {
        size_t blob = ((size_t)(mt * nch + kt)) << 14;
#pragma unroll
        for (int q = 0; q < 4; q++)
            s[seg * 4 + q][r] = quant_word(*(const float4*)(xr + kt * 128 + seg * 16 + q * 4),
                                           sc, -128.f, 127.f);
        __syncthreads();
#pragma unroll
        for (int q = 0; q < 4; q++) {
            int kw = q * 8 + warp;
            *(int*)(xqt + blob + kw * 512 + (rbase + lane) * 4) = s[kw][lane];
        }
        __syncthreads();
    }
}

// ======================= rmsnorm + act quant -> hqt blobs =======================
__global__ void rmsnorm_quant(const float* __restrict__ h, const float* __restrict__ lnw,
                              signed char* __restrict__ hqt, float* __restrict__ hinv) {
    __shared__ float sh[Idim];
    __shared__ float red[256];
    int tid = threadIdx.x;
    int row = blockIdx.x;
    int mt = row >> 7, rloc = row & 127;
    long base = (long)row * Idim;
    float ss = 0.f;
    for (int i = tid; i < Idim; i += 256) {
        float v = h[base + i];
        sh[i] = v;
        ss += v * v;
    }
    red[tid] = ss;
    __syncthreads();
    for (int o = 128; o > 0; o >>= 1) {
        if (tid < o) red[tid] += red[tid + o];
        __syncthreads();
    }
    float rs = rsqrtf(red[0] / (float)Idim + 1e-6f);
    __syncthreads();
    float mx = 0.f;
    for (int i = tid; i < Idim; i += 256) {
        float hn = lnw[i] * sh[i] * rs;
        sh[i] = hn;
        mx = fmaxf(mx, fabsf(hn));
    }
    red[tid] = mx;
    __syncthreads();
    for (int o = 128; o > 0; o >>= 1) {
        if (tid < o) red[tid] = fmaxf(red[tid], red[tid + o]);
        __syncthreads();
    }
    float cm = fmaxf(red[0], 1e-5f);
    float s = 127.f / cm;
    if (tid == 0) hinv[row] = cm * (1.f / 127.f);
    __syncthreads();
    for (int g = tid; g < Idim / 16; g += 256) {
        int kt = g >> 3, c16 = g & 7;
        size_t blob = ((size_t)(mt * NCH_I + kt)) << 14;
#pragma unroll
        for (int qi = 0; qi < 4; qi++) {
            const float* p = sh + g * 16 + qi * 4;
            int w = quant_word(make_float4(p[0], p[1], p[2], p[3]), s, -128.f, 127.f);
            *(int*)(hqt + blob + (c16 * 4 + qi) * 512 + rloc * 4) = w;
        }
    }
}

// ======================= pure-dp4a GEMM =======================
// stage: At@0 16K | B0t@16K 16K | [B1t@32K 16K]    (all [kw32][128 words])
// 16 warps, warp w: rows (w&3)*32..+31, cols (w>>2)*32..+31; thread: 8 rows x 4 cols.
template<int NB, int STAGES>
__global__ void __launch_bounds__(512, 1)
gemm_dp4a(const signed char* __restrict__ At,
          const signed char* __restrict__ B0t, const signed char* __restrict__ B1t,
          float* __restrict__ C, int NC, int Nout,
          const float* __restrict__ rowinv, int iw0, int iw1)
{
    extern __shared__ char smem[];
    char* sp = (char*)(((uintptr_t)smem + 1023u) & ~(uintptr_t)1023u);
    const uint32_t db = smem_u32(sp);
    constexpr uint32_t STAGE_B = (NB == 2) ? 49152u : 32768u;
    const uint32_t mb = db + STAGES * STAGE_B;
    const int tid = threadIdx.x, lane = tid & 31, wid = tid >> 5;
    const int m0 = blockIdx.x * 128, n0 = blockIdx.y * 128;

    if (tid == 0)
        for (int s = 0; s < STAGES; s++) MBAR_INIT(mb + s * 8, 1);
    __syncthreads();

    const size_t blobA = ((size_t)blockIdx.x * NC) << 14;
    const size_t blobB = ((size_t)blockIdx.y * NC) << 14;

    auto issue = [&](int chunk) {
        if (tid != 0) return;
        int st = chunk % STAGES;
        uint32_t bar = mb + st * 8;
        uint32_t base = db + st * STAGE_B;
        MBAR_EXPECT(bar, STAGE_B);
        size_t co = (size_t)chunk << 14;
        bulk_g2s(base,          At  + blobA + co, 16384, bar);
        bulk_g2s(base + 16384,  B0t + blobB + co, 16384, bar);
        if (NB == 2) bulk_g2s(base + 32768, B1t + blobB + co, 16384, bar);
    };

    const int drow = (wid & 3) * 32 + ((lane >> 3) << 3);
    const int dcol = ((wid >> 2) << 5) + ((lane & 7) << 2);
    int dac0[8][4], dac1[8][4];
#pragma unroll
    for (int i = 0; i < 8; i++)
#pragma unroll
        for (int j = 0; j < 4; j++) { dac0[i][j] = 0; if (NB == 2) dac1[i][j] = 0; }

    int fill = 0;
    for (; fill < STAGES - 1 && fill < NC; fill++) issue(fill);

    for (int ch = 0; ch < NC; ch++) {
        if (fill < NC) { issue(fill); fill++; }
        int st = ch % STAGES;
        mbar_wait(mb + st * 8, (ch / STAGES) & 1);

        const char* at  = sp + (size_t)st * STAGE_B + drow * 4;
        const char* bt0 = sp + (size_t)st * STAGE_B + 16384u + dcol * 4;
        const char* bt1 = sp + (size_t)st * STAGE_B + 32768u + dcol * 4;
#pragma unroll 4
        for (int kk = 0; kk < 32; kk++) {
            int4 a0 = *(const int4*)(at + kk * 512);
            int4 a1 = *(const int4*)(at + kk * 512 + 16);
            int4 bv0 = *(const int4*)(bt0 + kk * 512);
            int a[8] = {a0.x, a0.y, a0.z, a0.w, a1.x, a1.y, a1.z, a1.w};
            int b0w[4] = {bv0.x, bv0.y, bv0.z, bv0.w};
#pragma unroll
            for (int i = 0; i < 8; i++)
#pragma unroll
                for (int j = 0; j < 4; j++)
                    dac0[i][j] = __dp4a(a[i], b0w[j], dac0[i][j]);
            if (NB == 2) {
                int4 bv1 = *(const int4*)(bt1 + kk * 512);
                int b1w[4] = {bv1.x, bv1.y, bv1.z, bv1.w};
#pragma unroll
                for (int i = 0; i < 8; i++)
#pragma unroll
                    for (int j = 0; j < 4; j++)
                        dac1[i][j] = __dp4a(a[i], b1w[j], dac1[i][j]);
            }
        }
        __syncthreads();
    }

    // ======== epilogue ========
    float wg0 = g_winv[iw0], wu0 = (NB == 2) ? g_winv[iw1] : 0.f;
    int cbase = n0 + dcol;
#pragma unroll
    for (int i = 0; i < 8; i++) {
        int r = m0 + drow + i;
        float ai = rowinv[r];
        float* crow = C + (size_t)r * Nout + cbase;
        if (NB == 2) {
            float sg = ai * wg0, su = ai * wu0;
            float4 o;
            float g0 = (float)dac0[i][0] * sg, u0 = (float)dac1[i][0] * su;
            float g1 = (float)dac0[i][1] * sg, u1 = (float)dac1[i][1] * su;
            float g2 = (float)dac0[i][2] * sg, u2 = (float)dac1[i][2] * su;
            float g3 = (float)dac0[i][3] * sg, u3 = (float)dac1[i][3] * su;
            o.x = (g0 / (1.f + expf(-g0))) * u0;
            o.y = (g1 / (1.f + expf(-g1))) * u1;
            o.z = (g2 / (1.f + expf(-g2))) * u2;
            o.w = (g3 / (1.f + expf(-g3))) * u3;
            *(float4*)crow = o;
        } else {
            float sc = ai * wg0;
            float4 o;
            o.x = (float)dac0[i][0] * sc;
            o.y = (float)dac0[i][1] * sc;
            o.z = (float)dac0[i][2] * sc;
            o.w = (float)dac0[i][3] * sc;
            *(float4*)crow = o;
        }
    }
}

// ======================= launch =======================
extern "C" void kernel_launch(void* const* d_in, const int* in_sizes, int n_in,
                              void* d_out, int out_size) {
    const float* x   = (const float*)d_in[0];
    const float* wg  = (const float*)d_in[1];
    const float* wu  = (const float*)d_in[2];
    const float* wd  = (const float*)d_in[3];
    const float* lnw = (const float*)d_in[4];
    float* out = (float*)d_out;

    signed char *wqg, *wqu, *wqd, *xqt, *hqt;
    float *gbuf, *ainv, *hinv;
    cudaGetSymbolAddress((void**)&wqg, g_wqg);
    cudaGetSymbolAddress((void**)&wqu, g_wqu);
    cudaGetSymbolAddress((void**)&wqd, g_wqd);
    cudaGetSymbolAddress((void**)&xqt, g_xqt);
    cudaGetSymbolAddress((void**)&hqt, g_hqt);
    cudaGetSymbolAddress((void**)&gbuf, g_gbuf);
    cudaGetSymbolAddress((void**)&ainv, g_ainv);
    cudaGetSymbolAddress((void**)&hinv, g_hinv);

    const int SMEM2 = 4 * 49152 + 1024 + 64;   // 197,696
    const int SMEM1 = 6 * 32768 + 1024 + 64;   // 197,696
    cudaFuncSetAttribute(gemm_dp4a<2, 4>, cudaFuncAttributeMaxDynamicSharedMemorySize, SMEM2);
    cudaFuncSetAttribute(gemm_dp4a<1, 6>, cudaFuncAttributeMaxDynamicSharedMemorySize, SMEM1);

    const long NWl = (long)NW;

    // 0: weight scales
    absmean_all<<<dim3(2048, 3), 256>>>(wg, wu, wd, NWl);
    // 1: all three weight quants -> transposed blobs
    quant_weight_all<<<dim3(2752, 3), 256>>>(wg, wu, wd);
    // 2: act quant -> transposed blobs
    quant_act_t<<<Tdim / 32, 256>>>(x, xqt, ainv, Hdim, NCH_H);
    // 3 (ncu slot): fused gate+up pure-dp4a GEMM -> h = silu(g)*u  [T, I]
    gemm_dp4a<2, 4><<<dim3(Tdim / 128, Idim / 128), 512, SMEM2>>>(
        xqt, wqg, wqu, gbuf, NCH_H, Idim, ainv, 0, 1);
    // 4: rmsnorm + act quant -> hqt blobs
    rmsnorm_quant<<<Tdim, 256>>>(gbuf, lnw, hqt, hinv);
    // 5: down GEMM -> out [T, H]
    gemm_dp4a<1, 6><<<dim3(Tdim / 128, Hdim / 128), 512, SMEM1>>>(
        hqt, wqd, wqd, out, NCH_I, Hdim, hinv, 2, 2);
}

// round 13
// speedup vs baseline: 1.5147x; 1.5147x over previous
#include <cuda_runtime.h>
#include <math.h>
#include <stdint.h>

#define Tdim 4096
#define Hdim 4096
#define Idim 11008
#define NW ((size_t)Idim*(size_t)Hdim)
#define NCH_H 32            // Hdim/128
#define NCH_I 86            // Idim/128

// ---- static device scratch ----
// A blobs (16KB per (mtile128, chunk)): [0,8K)... actually [0,16K) kmaj swz rows0..127; At separate.
// B blobs (8KB per (ntile64, chunk)): [0,4K) rows(cols)0..31 kmaj swz; [4K,8K) cols32..63 transposed [kw32][32w]
__device__ __align__(16) signed char g_wqg[NW];
__device__ __align__(16) signed char g_wqu[NW];
__device__ __align__(16) signed char g_wqd[NW];
__device__ __align__(16) signed char g_xq [(size_t)Tdim*Hdim];   // A kmaj swz blobs (16K/chunk)
__device__ __align__(16) signed char g_xqt[(size_t)Tdim*Hdim];   // At word blobs [kw*512+row*4]
__device__ __align__(16) signed char g_hq [(size_t)Tdim*Idim];
__device__ __align__(16) signed char g_hqt[(size_t)Tdim*Idim];
__device__ float g_gbuf[(size_t)Tdim*Idim];
__device__ float g_ainv[Tdim];
__device__ float g_hinv[Tdim];
__device__ float g_partial[3][2048];
__device__ float g_wscale[3];
__device__ float g_winv[3];
__device__ unsigned g_cnt = 0;

// ======================= PTX helpers =======================
__device__ __forceinline__ uint32_t smem_u32(const void* p) {
    uint32_t a;
    asm("{ .reg .u64 t; cvta.to.shared.u64 t, %1; cvt.u32.u64 %0, t; }" : "=r"(a) : "l"(p));
    return a;
}
#define MBAR_INIT(a, c) asm volatile("mbarrier.init.shared.b64 [%0], %1;" :: "r"(a), "r"(c) : "memory")
#define MBAR_EXPECT(a, b) asm volatile("mbarrier.arrive.expect_tx.shared.b64 _, [%0], %1;" :: "r"(a), "r"(b) : "memory")
__device__ __forceinline__ void mbar_wait(uint32_t addr, uint32_t parity) {
    asm volatile(
        "{\n\t.reg .pred P;\n\t"
        "LW_%=:\n\t"
        "mbarrier.try_wait.parity.acquire.cta.shared::cta.b64 P, [%0], %1, 0x989680;\n\t"
        "@P bra.uni LD_%=;\n\t"
        "bra.uni LW_%=;\n\t"
        "LD_%=:\n\t}"
        :: "r"(addr), "r"(parity) : "memory");
}
__device__ __forceinline__ void bulk_g2s(uint32_t dst, const void* src, uint32_t bytes, uint32_t mbar) {
    asm volatile("cp.async.bulk.shared::cluster.global.mbarrier::complete_tx::bytes [%0], [%1], %2, [%3];"
        :: "r"(dst), "l"(src), "r"(bytes), "r"(mbar) : "memory");
}
#define LDSM4(r, a) asm volatile( \
    "ldmatrix.sync.aligned.m8n8.x4.shared.b16 {%0,%1,%2,%3}, [%4];" \
    : "=r"((r)[0]), "=r"((r)[1]), "=r"((r)[2]), "=r"((r)[3]) : "r"(a))
#define MMA_S8(d, a, b0, b1) asm volatile( \
    "mma.sync.aligned.m16n8k32.row.col.s32.s8.s8.s32 " \
    "{%0,%1,%2,%3}, {%4,%5,%6,%7}, {%8,%9}, {%0,%1,%2,%3};" \
    : "+r"((d)[0]), "+r"((d)[1]), "+r"((d)[2]), "+r"((d)[3]) \
    : "r"((a)[0]), "r"((a)[1]), "r"((a)[2]), "r"((a)[3]), "r"(b0), "r"(b1))

__device__ __forceinline__ int quant_word(float4 v, float sc, float lo, float hi) {
    int b0 = (int)fminf(hi, fmaxf(lo, rintf(v.x * sc)));
    int b1 = (int)fminf(hi, fmaxf(lo, rintf(v.y * sc)));
    int b2 = (int)fminf(hi, fmaxf(lo, rintf(v.z * sc)));
    int b3 = (int)fminf(hi, fmaxf(lo, rintf(v.w * sc)));
    return (b0 & 0xFF) | ((b1 & 0xFF) << 8) | ((b2 & 0xFF) << 16) | (b3 << 24);
}

// ======================= absmean + finalize =======================
__global__ void absmean_all(const float* __restrict__ wg, const float* __restrict__ wu,
                            const float* __restrict__ wd, long n) {
    __shared__ float red[256];
    __shared__ double redd[256];
    __shared__ bool amLast;
    int which = blockIdx.y;
    const float* w = which == 0 ? wg : (which == 1 ? wu : wd);
    float s = 0.f;
    long stride = (long)gridDim.x * blockDim.x;
    for (long i = (long)blockIdx.x * blockDim.x + threadIdx.x; i < n; i += stride)
        s += fabsf(w[i]);
    red[threadIdx.x] = s;
    __syncthreads();
    for (int o = 128; o > 0; o >>= 1) {
        if (threadIdx.x < o) red[threadIdx.x] += red[threadIdx.x + o];
        __syncthreads();
    }
    if (threadIdx.x == 0) {
        g_partial[which][blockIdx.x] = red[0];
        __threadfence();
        unsigned t = atomicAdd(&g_cnt, 1u);
        amLast = (t == gridDim.x * 3 - 1);
    }
    __syncthreads();
    if (amLast) {
        for (int m = 0; m < 3; m++) {
            double s2 = 0.0;
            for (int i = threadIdx.x; i < 2048; i += 256) s2 += (double)g_partial[m][i];
            redd[threadIdx.x] = s2;
            __syncthreads();
            for (int o = 128; o > 0; o >>= 1) {
                if (threadIdx.x < o) redd[threadIdx.x] += redd[threadIdx.x + o];
                __syncthreads();
            }
            if (threadIdx.x == 0) {
                float mean = (float)(redd[0] / (double)n);
                float cm = fmaxf(mean, 1e-5f);
                g_wscale[m] = 1.f / cm;
                g_winv[m] = cm;
            }
            __syncthreads();
        }
        if (threadIdx.x == 0) g_cnt = 0;
    }
}

// ======================= weight quant -> 8KB B blobs per (ntile64, chunk) ===========
__global__ void quant_weight_all(const float* __restrict__ wg, const float* __restrict__ wu,
                                 const float* __restrict__ wd) {
    __shared__ int s[32][132];
    int which = blockIdx.y;
    const float* w; signed char* outb; int Kf, ktc;
    if (which == 0)      { w = wg; outb = g_wqg; Kf = Hdim; ktc = NCH_H; }
    else if (which == 1) { w = wu; outb = g_wqu; Kf = Hdim; ktc = NCH_H; }
    else                 { w = wd; outb = g_wqd; Kf = Idim; ktc = NCH_I; }
    int bx = blockIdx.x;
    int kc = bx % ktc, nt128 = bx / ktc;
    int kc0 = kc * 128, n0 = nt128 * 128;
    float sw = g_wscale[which];
    int t = threadIdx.x;
    int r = t >> 1, h = t & 1;          // r = local n-row 0..127
    const float* wr = w + (size_t)(n0 + r) * Kf + kc0 + h * 64;
    int words[16];
#pragma unroll
    for (int q = 0; q < 16; q++) {
        words[q] = quant_word(*(const float4*)(wr + q * 4), sw, -1.f, 1.f);
        s[h * 16 + q][r] = words[q];
    }
    // kmaj halves: rows with (r & 63) < 32 go to their ntile64's blob [0,4K)
    if ((r & 63) < 32) {
        int nt64 = nt128 * 2 + (r >> 6);
        int rloc = r & 31;
        signed char* blob = outb + (((size_t)nt64 * ktc + kc) << 13);
#pragma unroll
        for (int qq = 0; qq < 4; qq++) {
            int c16 = h * 4 + qq;
            *(int4*)(blob + rloc * 128 + ((c16 ^ (rloc & 7)) << 4)) =
                make_int4(words[qq*4], words[qq*4+1], words[qq*4+2], words[qq*4+3]);
        }
    }
    __syncthreads();
    // transposed halves: cols (r&63)>=32, layout [kw32][32 words] at blob+4096
    int kw = t >> 3, seg = t & 7;
    int nt64 = nt128 * 2 + (seg >> 2);
    int cseg = seg & 3;                 // 4 segs of 8 cols within the 32 transposed cols
    signed char* blob = outb + (((size_t)nt64 * ktc + kc) << 13);
    int srcbase = (seg >> 2) * 64 + 32 + cseg * 8;
    signed char* tp = blob + 4096 + kw * 128 + cseg * 32;
    *(int4*)tp = make_int4(s[kw][srcbase+0], s[kw][srcbase+1], s[kw][srcbase+2], s[kw][srcbase+3]);
    *(int4*)(tp+16) = make_int4(s[kw][srcbase+4], s[kw][srcbase+5], s[kw][srcbase+6], s[kw][srcbase+7]);
}

// ======================= act quant -> A blob (swz) + At blob (transposed) =======================
__global__ void quant_act_t(const float* __restrict__ x, signed char* __restrict__ xq,
                            signed char* __restrict__ xqt, float* __restrict__ ainv,
                            int Kf, int nch) {
    __shared__ float rscale[32];
    __shared__ float rinvs[32];
    __shared__ int s[32][33];
    int t = threadIdx.x, warp = t >> 5, lane = t & 31;
    int row0 = blockIdx.x * 32;
    int mt = row0 >> 7, rbase = row0 & 127;
#pragma unroll
    for (int rr = 0; rr < 4; rr++) {
        int r = warp * 4 + rr;
        const float4* xr = (const float4*)(x + (size_t)(row0 + r) * Kf);
        float mx = 0.f;
        for (int i = lane; i < Kf / 4; i += 32) {
            float4 v = xr[i];
            mx = fmaxf(mx, fmaxf(fmaxf(fabsf(v.x), fabsf(v.y)), fmaxf(fabsf(v.z), fabsf(v.w))));
        }
#pragma unroll
        for (int o = 16; o > 0; o >>= 1) mx = fmaxf(mx, __shfl_xor_sync(0xFFFFFFFFu, mx, o));
        if (lane == 0) {
            float cm = fmaxf(mx, 1e-5f);
            rscale[r] = 127.f / cm;
            rinvs[r] = cm * (1.f / 127.f);
        }
    }
    __syncthreads();
    if (t < 32) ainv[row0 + t] = rinvs[t];
    int r = t >> 3, seg = t & 7;
    int rloc = rbase + r;
    float sc = rscale[r];
    const float* xr = x + (size_t)(row0 + r) * Kf;
    for (int kt = 0; kt < nch; kt++) {
        size_t blob = ((size_t)(mt * nch + kt)) << 14;
        int words[4];
#pragma unroll
        for (int q = 0; q < 4; q++) {
            words[q] = quant_word(*(const float4*)(xr + kt * 128 + seg * 16 + q * 4), sc, -128.f, 127.f);
            s[seg * 4 + q][r] = words[q];
        }
        *(int4*)(xq + blob + rloc * 128 + ((seg ^ (rloc & 7)) << 4)) =
            make_int4(words[0], words[1], words[2], words[3]);
        __syncthreads();
#pragma unroll
        for (int q = 0; q < 4; q++) {
            int kw = q * 8 + warp;
            *(int*)(xqt + blob + kw * 512 + (rbase + lane) * 4) = s[kw][lane];
        }
        __syncthreads();
    }
}

// ======================= rmsnorm + act quant -> hq/hqt blobs =======================
__global__ void rmsnorm_quant(const float* __restrict__ h, const float* __restrict__ lnw,
                              signed char* __restrict__ hq, signed char* __restrict__ hqt,
                              float* __restrict__ hinv) {
    __shared__ float sh[Idim];
    __shared__ float red[256];
    int tid = threadIdx.x;
    int row = blockIdx.x;
    int mt = row >> 7, rloc = row & 127;
    long base = (long)row * Idim;
    float ss = 0.f;
    for (int i = tid; i < Idim; i += 256) {
        float v = h[base + i];
        sh[i] = v;
        ss += v * v;
    }
    red[tid] = ss;
    __syncthreads();
    for (int o = 128; o > 0; o >>= 1) {
        if (tid < o) red[tid] += red[tid + o];
        __syncthreads();
    }
    float rs = rsqrtf(red[0] / (float)Idim + 1e-6f);
    __syncthreads();
    float mx = 0.f;
    for (int i = tid; i < Idim; i += 256) {
        float hn = lnw[i] * sh[i] * rs;
        sh[i] = hn;
        mx = fmaxf(mx, fabsf(hn));
    }
    red[tid] = mx;
    __syncthreads();
    for (int o = 128; o > 0; o >>= 1) {
        if (tid < o) red[tid] = fmaxf(red[tid], red[tid + o]);
        __syncthreads();
    }
    float cm = fmaxf(red[0], 1e-5f);
    float s = 127.f / cm;
    if (tid == 0) hinv[row] = cm * (1.f / 127.f);
    __syncthreads();
    for (int g = tid; g < Idim / 16; g += 256) {
        int kt = g >> 3, c16 = g & 7;
        size_t blob = ((size_t)(mt * NCH_I + kt)) << 14;
        int w[4];
#pragma unroll
        for (int qi = 0; qi < 4; qi++) {
            const float* p = sh + g * 16 + qi * 4;
            w[qi] = quant_word(make_float4(p[0], p[1], p[2], p[3]), s, -128.f, 127.f);
            *(int*)(hqt + blob + (c16 * 4 + qi) * 512 + rloc * 4) = w[qi];
        }
        *(int4*)(hq + blob + rloc * 128 + ((c16 ^ (rloc & 7)) << 4)) =
            make_int4(w[0], w[1], w[2], w[3]);
    }
}

// ======================= hybrid GEMM: 128x64 tile, 2 CTAs/SM =======================
// stage NB=2: A@0 16K | At@16K 16K | B0 blob@32K 8K | B1 blob@40K 8K   (48K)
// stage NB=1: A@0 16K | At@16K 16K | B  blob@32K 8K                    (40K)
// warps 4-7: IMMA cols [0,32);  warps 0-3: dp4a cols [32,64).
template<int NB, int STAGES>
__global__ void __launch_bounds__(256, 2)
gemm_hyb(const signed char* __restrict__ A, const signed char* __restrict__ At,
         const signed char* __restrict__ B0, const signed char* __restrict__ B1,
         float* __restrict__ C, int NC, int Nout,
         const float* __restrict__ rowinv, int iw0, int iw1)
{
    extern __shared__ char smem[];
    char* sp = (char*)(((uintptr_t)smem + 1023u) & ~(uintptr_t)1023u);
    const uint32_t db = smem_u32(sp);
    constexpr uint32_t STAGE_B = (NB == 2) ? 49152u : 40960u;
    const uint32_t mb = db + STAGES * STAGE_B;
    const int tid = threadIdx.x, lane = tid & 31, wid = tid >> 5;
    const int m0 = blockIdx.x * 128, n0 = blockIdx.y * 64;

    if (tid == 0)
        for (int s = 0; s < STAGES; s++) MBAR_INIT(mb + s * 8, 1);
    __syncthreads();

    const size_t blobA = ((size_t)blockIdx.x * NC) << 14;
    const size_t blobB = ((size_t)blockIdx.y * NC) << 13;

    auto issue = [&](int chunk) {
        if (tid != 0) return;
        int st = chunk % STAGES;
        uint32_t bar = mb + st * 8;
        uint32_t base = db + st * STAGE_B;
        MBAR_EXPECT(bar, STAGE_B);
        bulk_g2s(base,          A  + blobA + ((size_t)chunk << 14), 16384, bar);
        bulk_g2s(base + 16384,  At + blobA + ((size_t)chunk << 14), 16384, bar);
        bulk_g2s(base + 32768,  B0 + blobB + ((size_t)chunk << 13), 8192, bar);
        if (NB == 2) bulk_g2s(base + 40960, B1 + blobB + ((size_t)chunk << 13), 8192, bar);
    };

    auto swz = [](int row, int c16) -> uint32_t {
        return (uint32_t)(row * 128 + ((c16 ^ (row & 7)) << 4));
    };

    // MMA-side state (warps 4..7): rows wm*32, cols 0..31
    const int wm = wid - 4;
    const int arow = (lane & 7) + ((lane & 8) ? 8 : 0);
    const int acol = (lane >> 4);
    const int brow = (lane & 7) + ((lane & 16) ? 8 : 0);
    const int bcol = ((lane >> 3) & 1);
    int acc[NB][2][4][4];
#pragma unroll
    for (int b = 0; b < NB; b++)
#pragma unroll
        for (int mt = 0; mt < 2; mt++)
#pragma unroll
            for (int n8 = 0; n8 < 4; n8++)
#pragma unroll
                for (int q = 0; q < 4; q++) acc[b][mt][n8][q] = 0;

    // dp4a-side state (warps 0..3): rows wid*32, cols 32..63 (transposed region)
    const int drow = wid * 32 + ((lane >> 3) << 3);
    const int dcol = (lane & 7) << 2;
    int dac0[8][4], dac1[8][4];
#pragma unroll
    for (int i = 0; i < 8; i++)
#pragma unroll
        for (int j = 0; j < 4; j++) { dac0[i][j] = 0; if (NB == 2) dac1[i][j] = 0; }

    int fill = 0;
    for (; fill < STAGES - 1 && fill < NC; fill++) issue(fill);

    for (int ch = 0; ch < NC; ch++) {
        if (fill < NC) { issue(fill); fill++; }
        int st = ch % STAGES;
        mbar_wait(mb + st * 8, (ch / STAGES) & 1);

        uint32_t sboff = (uint32_t)st * STAGE_B;
        if (wid >= 4) {
            uint32_t abase = db + sboff;
#pragma unroll
            for (int s = 0; s < 4; s++) {
                uint32_t af[2][4];
#pragma unroll
                for (int mt = 0; mt < 2; mt++) {
                    int row = wm * 32 + mt * 16 + arow;
                    LDSM4(af[mt], abase + swz(row, s * 2 + acol));
                }
#pragma unroll
                for (int b = 0; b < NB; b++) {
                    uint32_t bb = abase + 32768u + (uint32_t)b * 8192u;   // kmaj part @ +0
#pragma unroll
                    for (int nt = 0; nt < 2; nt++) {
                        uint32_t bf[4];
                        int row = nt * 16 + brow;                          // B rows 0..31
                        LDSM4(bf, bb + swz(row, s * 2 + bcol));
#pragma unroll
                        for (int mt = 0; mt < 2; mt++) {
                            MMA_S8(acc[b][mt][nt * 2 + 0], af[mt], bf[0], bf[1]);
                            MMA_S8(acc[b][mt][nt * 2 + 1], af[mt], bf[2], bf[3]);
                        }
                    }
                }
            }
        } else {
            const char* at  = sp + sboff + 16384u + drow * 4;
            const char* bt0 = sp + sboff + 32768u + 4096u + dcol * 4;
            const char* bt1 = sp + sboff + 40960u + 4096u + dcol * 4;
#pragma unroll 4
            for (int kk = 0; kk < 32; kk++) {
                int4 a0 = *(const int4*)(at + kk * 512);
                int4 a1 = *(const int4*)(at + kk * 512 + 16);
                int4 bv0 = *(const int4*)(bt0 + kk * 128);
                int a[8] = {a0.x, a0.y, a0.z, a0.w, a1.x, a1.y, a1.z, a1.w};
                int b0w[4] = {bv0.x, bv0.y, bv0.z, bv0.w};
#pragma unroll
                for (int i = 0; i < 8; i++)
#pragma unroll
                    for (int j = 0; j < 4; j++)
                        dac0[i][j] = __dp4a(a[i], b0w[j], dac0[i][j]);
                if (NB == 2) {
                    int4 bv1 = *(const int4*)(bt1 + kk * 128);
                    int b1w[4] = {bv1.x, bv1.y, bv1.z, bv1.w};
#pragma unroll
                    for (int i = 0; i < 8; i++)
#pragma unroll
                        for (int j = 0; j < 4; j++)
                            dac1[i][j] = __dp4a(a[i], b1w[j], dac1[i][j]);
                }
            }
        }
        __syncthreads();
    }

    // ======== epilogue ========
    float wg0 = g_winv[iw0], wu0 = (NB == 2) ? g_winv[iw1] : 0.f;
    if (wid >= 4) {
#pragma unroll
        for (int mt = 0; mt < 2; mt++) {
            int r = m0 + wm * 32 + mt * 16 + (lane >> 2);
            float ai0 = rowinv[r], ai1 = rowinv[r + 8];
            float* crow0 = C + (size_t)r * Nout;
            float* crow1 = C + (size_t)(r + 8) * Nout;
            if (NB == 2) {
                float sg0 = ai0 * wg0, su0 = ai0 * wu0;
                float sg1 = ai1 * wg0, su1 = ai1 * wu0;
#pragma unroll
                for (int n8 = 0; n8 < 4; n8++) {
                    int c = n0 + n8 * 8 + (lane & 3) * 2;
                    float g00 = (float)acc[0][mt][n8][0] * sg0;
                    float g01 = (float)acc[0][mt][n8][1] * sg0;
                    float g10 = (float)acc[0][mt][n8][2] * sg1;
                    float g11 = (float)acc[0][mt][n8][3] * sg1;
                    float u00 = (float)acc[1][mt][n8][0] * su0;
                    float u01 = (float)acc[1][mt][n8][1] * su0;
                    float u10 = (float)acc[1][mt][n8][2] * su1;
                    float u11 = (float)acc[1][mt][n8][3] * su1;
                    float2 o0, o1;
                    o0.x = (g00 / (1.f + expf(-g00))) * u00;
                    o0.y = (g01 / (1.f + expf(-g01))) * u01;
                    o1.x = (g10 / (1.f + expf(-g10))) * u10;
                    o1.y = (g11 / (1.f + expf(-g11))) * u11;
                    *(float2*)(crow0 + c) = o0;
                    *(float2*)(crow1 + c) = o1;
                }
            } else {
                float s0 = ai0 * wg0, s1 = ai1 * wg0;
#pragma unroll
                for (int n8 = 0; n8 < 4; n8++) {
                    int c = n0 + n8 * 8 + (lane & 3) * 2;
                    float2 o0, o1;
                    o0.x = (float)acc[0][mt][n8][0] * s0;
                    o0.y = (float)acc[0][mt][n8][1] * s0;
                    o1.x = (float)acc[0][mt][n8][2] * s1;
                    o1.y = (float)acc[0][mt][n8][3] * s1;
                    *(float2*)(crow0 + c) = o0;
                    *(float2*)(crow1 + c) = o1;
                }
            }
        }
    } else {
        int cbase = n0 + 32 + dcol;
#pragma unroll
        for (int i = 0; i < 8; i++) {
            int r = m0 + drow + i;
            float ai = rowinv[r];
            float* crow = C + (size_t)r * Nout + cbase;
            if (NB == 2) {
                float sg = ai * wg0, su = ai * wu0;
                float4 o;
                float g0 = (float)dac0[i][0] * sg, u0 = (float)dac1[i][0] * su;
                float g1 = (float)dac0[i][1] * sg, u1 = (float)dac1[i][1] * su;
                float g2 = (float)dac0[i][2] * sg, u2 = (float)dac1[i][2] * su;
                float g3 = (float)dac0[i][3] * sg, u3 = (float)dac1[i][3] * su;
                o.x = (g0 / (1.f + expf(-g0))) * u0;
                o.y = (g1 / (1.f + expf(-g1))) * u1;
                o.z = (g2 / (1.f + expf(-g2))) * u2;
                o.w = (g3 / (1.f + expf(-g3))) * u3;
                *(float4*)crow = o;
            } else {
                float sc = ai * wg0;
                float4 o;
                o.x = (float)dac0[i][0] * sc;
                o.y = (float)dac0[i][1] * sc;
                o.z = (float)dac0[i][2] * sc;
                o.w = (float)dac0[i][3] * sc;
                *(float4*)crow = o;
            }
        }
    }
}

// ======================= launch =======================
extern "C" void kernel_launch(void* const* d_in, const int* in_sizes, int n_in,
                              void* d_out, int out_size) {
    const float* x   = (const float*)d_in[0];
    const float* wg  = (const float*)d_in[1];
    const float* wu  = (const float*)d_in[2];
    const float* wd  = (const float*)d_in[3];
    const float* lnw = (const float*)d_in[4];
    float* out = (float*)d_out;

    signed char *wqg, *wqu, *wqd, *xq, *xqt, *hq, *hqt;
    float *gbuf, *ainv, *hinv;
    cudaGetSymbolAddress((void**)&wqg, g_wqg);
    cudaGetSymbolAddress((void**)&wqu, g_wqu);
    cudaGetSymbolAddress((void**)&wqd, g_wqd);
    cudaGetSymbolAddress((void**)&xq, g_xq);
    cudaGetSymbolAddress((void**)&xqt, g_xqt);
    cudaGetSymbolAddress((void**)&hq, g_hq);
    cudaGetSymbolAddress((void**)&hqt, g_hqt);
    cudaGetSymbolAddress((void**)&gbuf, g_gbuf);
    cudaGetSymbolAddress((void**)&ainv, g_ainv);
    cudaGetSymbolAddress((void**)&hinv, g_hinv);

    const int SMEM2 = 2 * 49152 + 1024 + 64;   // 99,392 -> 2 CTAs/SM
    const int SMEM1 = 2 * 40960 + 1024 + 64;   // 82,984 -> 2 CTAs/SM
    cudaFuncSetAttribute(gemm_hyb<2, 2>, cudaFuncAttributeMaxDynamicSharedMemorySize, SMEM2);
    cudaFuncSetAttribute(gemm_hyb<1, 2>, cudaFuncAttributeMaxDynamicSharedMemorySize, SMEM1);

    const long NWl = (long)NW;

    // 0: weight scales
    absmean_all<<<dim3(2048, 3), 256>>>(wg, wu, wd, NWl);
    // 1: all three weight quants -> 8KB ntile64 blobs
    quant_weight_all<<<dim3(2752, 3), 256>>>(wg, wu, wd);
    // 2: act quant -> A + At blobs
    quant_act_t<<<Tdim / 32, 256>>>(x, xq, xqt, ainv, Hdim, NCH_H);
    // 3 (ncu slot): fused gate+up hybrid GEMM (128x64 tiles, 2 CTAs/SM) -> h = silu(g)*u
    gemm_hyb<2, 2><<<dim3(Tdim / 128, Idim / 64), 256, SMEM2>>>(
        xq, xqt, wqg, wqu, gbuf, NCH_H, Idim, ainv, 0, 1);
    // 4: rmsnorm + act quant -> hq/hqt blobs
    rmsnorm_quant<<<Tdim, 256>>>(gbuf, lnw, hq, hqt, hinv);
    // 5: down GEMM -> out [T, H]
    gemm_hyb<1, 2><<<dim3(Tdim / 128, Hdim / 64), 256, SMEM1>>>(
        hq, hqt, wqd, wqd, out, NCH_I, Hdim, hinv, 2, 2);
}

// round 14
// speedup vs baseline: 1.5518x; 1.0245x over previous
#include <cuda_runtime.h>
#include <math.h>
#include <stdint.h>

#define Tdim 4096
#define Hdim 4096
#define Idim 11008
#define NW ((size_t)Idim*(size_t)Hdim)
#define NCH_H 32            // Hdim/128
#define NCH_I 86            // Idim/128

// ---- static device scratch ----
// A blobs (16KB per (mtile128, chunk)): kmaj swz rows 0..127; At blobs [kw32][128 words].
// B blobs (8KB per (ntile64, chunk)): [0,4K) cols0..31 kmaj swz; [4K,8K) cols32..63 transposed [kw32][32w]
__device__ __align__(16) signed char g_wqg[NW];
__device__ __align__(16) signed char g_wqu[NW];
__device__ __align__(16) signed char g_wqd[NW];
__device__ __align__(16) signed char g_xq [(size_t)Tdim*Hdim];
__device__ __align__(16) signed char g_xqt[(size_t)Tdim*Hdim];
__device__ __align__(16) signed char g_hq [(size_t)Tdim*Idim];
__device__ __align__(16) signed char g_hqt[(size_t)Tdim*Idim];
__device__ float g_gbuf[(size_t)Tdim*Idim];
__device__ float g_ainv[Tdim];
__device__ float g_hinv[Tdim];
__device__ float g_partial[3][2048];
__device__ float g_wscale[3];
__device__ float g_winv[3];
__device__ unsigned g_cnt = 0;

// ======================= PTX helpers =======================
__device__ __forceinline__ uint32_t smem_u32(const void* p) {
    uint32_t a;
    asm("{ .reg .u64 t; cvta.to.shared.u64 t, %1; cvt.u32.u64 %0, t; }" : "=r"(a) : "l"(p));
    return a;
}
#define MBAR_INIT(a, c) asm volatile("mbarrier.init.shared.b64 [%0], %1;" :: "r"(a), "r"(c) : "memory")
#define MBAR_EXPECT(a, b) asm volatile("mbarrier.arrive.expect_tx.shared.b64 _, [%0], %1;" :: "r"(a), "r"(b) : "memory")
__device__ __forceinline__ void mbar_wait(uint32_t addr, uint32_t parity) {
    asm volatile(
        "{\n\t.reg .pred P;\n\t"
        "LW_%=:\n\t"
        "mbarrier.try_wait.parity.acquire.cta.shared::cta.b64 P, [%0], %1, 0x989680;\n\t"
        "@P bra.uni LD_%=;\n\t"
        "bra.uni LW_%=;\n\t"
        "LD_%=:\n\t}"
        :: "r"(addr), "r"(parity) : "memory");
}
__device__ __forceinline__ void bulk_g2s(uint32_t dst, const void* src, uint32_t bytes, uint32_t mbar) {
    asm volatile("cp.async.bulk.shared::cluster.global.mbarrier::complete_tx::bytes [%0], [%1], %2, [%3];"
        :: "r"(dst), "l"(src), "r"(bytes), "r"(mbar) : "memory");
}
#define LDSM4(r, a) asm volatile( \
    "ldmatrix.sync.aligned.m8n8.x4.shared.b16 {%0,%1,%2,%3}, [%4];" \
    : "=r"((r)[0]), "=r"((r)[1]), "=r"((r)[2]), "=r"((r)[3]) : "r"(a))
#define MMA_S8(d, a, b0, b1) asm volatile( \
    "mma.sync.aligned.m16n8k32.row.col.s32.s8.s8.s32 " \
    "{%0,%1,%2,%3}, {%4,%5,%6,%7}, {%8,%9}, {%0,%1,%2,%3};" \
    : "+r"((d)[0]), "+r"((d)[1]), "+r"((d)[2]), "+r"((d)[3]) \
    : "r"((a)[0]), "r"((a)[1]), "r"((a)[2]), "r"((a)[3]), "r"(b0), "r"(b1))
#define LDS128(v, a) asm volatile("ld.shared.v4.u32 {%0,%1,%2,%3}, [%4];" \
    : "=r"((v).x), "=r"((v).y), "=r"((v).z), "=r"((v).w) : "r"(a))

__device__ __forceinline__ int quant_word(float4 v, float sc, float lo, float hi) {
    int b0 = (int)fminf(hi, fmaxf(lo, rintf(v.x * sc)));
    int b1 = (int)fminf(hi, fmaxf(lo, rintf(v.y * sc)));
    int b2 = (int)fminf(hi, fmaxf(lo, rintf(v.z * sc)));
    int b3 = (int)fminf(hi, fmaxf(lo, rintf(v.w * sc)));
    return (b0 & 0xFF) | ((b1 & 0xFF) << 8) | ((b2 & 0xFF) << 16) | (b3 << 24);
}

// ======================= absmean + finalize (float4 loads) =======================
__global__ void absmean_all(const float* __restrict__ wg, const float* __restrict__ wu,
                            const float* __restrict__ wd, long n) {
    __shared__ float red[256];
    __shared__ double redd[256];
    __shared__ bool amLast;
    int which = blockIdx.y;
    const float* w = which == 0 ? wg : (which == 1 ? wu : wd);
    const float4* w4 = (const float4*)w;
    long n4 = n >> 2;
    float s = 0.f;
    long stride = (long)gridDim.x * blockDim.x;
    for (long i = (long)blockIdx.x * blockDim.x + threadIdx.x; i < n4; i += stride) {
        float4 v = w4[i];
        s += fabsf(v.x) + fabsf(v.y) + fabsf(v.z) + fabsf(v.w);
    }
    red[threadIdx.x] = s;
    __syncthreads();
    for (int o = 128; o > 0; o >>= 1) {
        if (threadIdx.x < o) red[threadIdx.x] += red[threadIdx.x + o];
        __syncthreads();
    }
    if (threadIdx.x == 0) {
        g_partial[which][blockIdx.x] = red[0];
        __threadfence();
        unsigned t = atomicAdd(&g_cnt, 1u);
        amLast = (t == gridDim.x * 3 - 1);
    }
    __syncthreads();
    if (amLast) {
        for (int m = 0; m < 3; m++) {
            double s2 = 0.0;
            for (int i = threadIdx.x; i < 2048; i += 256) s2 += (double)g_partial[m][i];
            redd[threadIdx.x] = s2;
            __syncthreads();
            for (int o = 128; o > 0; o >>= 1) {
                if (threadIdx.x < o) redd[threadIdx.x] += redd[threadIdx.x + o];
                __syncthreads();
            }
            if (threadIdx.x == 0) {
                float mean = (float)(redd[0] / (double)n);
                float cm = fmaxf(mean, 1e-5f);
                g_wscale[m] = 1.f / cm;
                g_winv[m] = cm;
            }
            __syncthreads();
        }
        if (threadIdx.x == 0) g_cnt = 0;
    }
}

// ======================= weight quant -> 8KB B blobs per (ntile64, chunk) ===========
__global__ void quant_weight_all(const float* __restrict__ wg, const float* __restrict__ wu,
                                 const float* __restrict__ wd) {
    __shared__ int s[32][133];
    int which = blockIdx.y;
    const float* w; signed char* outb; int Kf, ktc;
    if (which == 0)      { w = wg; outb = g_wqg; Kf = Hdim; ktc = NCH_H; }
    else if (which == 1) { w = wu; outb = g_wqu; Kf = Hdim; ktc = NCH_H; }
    else                 { w = wd; outb = g_wqd; Kf = Idim; ktc = NCH_I; }
    int bx = blockIdx.x;
    int kc = bx % ktc, nt128 = bx / ktc;
    int kc0 = kc * 128, n0 = nt128 * 128;
    float sw = g_wscale[which];
    int t = threadIdx.x;
    int r = t >> 1, h = t & 1;
    const float* wr = w + (size_t)(n0 + r) * Kf + kc0 + h * 64;
    int words[16];
#pragma unroll
    for (int q = 0; q < 16; q++) {
        words[q] = quant_word(*(const float4*)(wr + q * 4), sw, -1.f, 1.f);
        s[h * 16 + q][r] = words[q];
    }
    if ((r & 63) < 32) {
        int nt64 = nt128 * 2 + (r >> 6);
        int rloc = r & 31;
        signed char* blob = outb + (((size_t)nt64 * ktc + kc) << 13);
#pragma unroll
        for (int qq = 0; qq < 4; qq++) {
            int c16 = h * 4 + qq;
            *(int4*)(blob + rloc * 128 + ((c16 ^ (rloc & 7)) << 4)) =
                make_int4(words[qq*4], words[qq*4+1], words[qq*4+2], words[qq*4+3]);
        }
    }
    __syncthreads();
    int kw = t >> 3, seg = t & 7;
    int nt64 = nt128 * 2 + (seg >> 2);
    int cseg = seg & 3;
    signed char* blob = outb + (((size_t)nt64 * ktc + kc) << 13);
    int srcbase = (seg >> 2) * 64 + 32 + cseg * 8;
    signed char* tp = blob + 4096 + kw * 128 + cseg * 32;
    *(int4*)tp = make_int4(s[kw][srcbase+0], s[kw][srcbase+1], s[kw][srcbase+2], s[kw][srcbase+3]);
    *(int4*)(tp+16) = make_int4(s[kw][srcbase+4], s[kw][srcbase+5], s[kw][srcbase+6], s[kw][srcbase+7]);
}

// ======================= act quant -> A blob (swz) + At blob (transposed) =======================
__global__ void quant_act_t(const float* __restrict__ x, signed char* __restrict__ xq,
                            signed char* __restrict__ xqt, float* __restrict__ ainv,
                            int Kf, int nch) {
    __shared__ float rscale[32];
    __shared__ float rinvs[32];
    __shared__ int s[32][33];
    int t = threadIdx.x, warp = t >> 5, lane = t & 31;
    int row0 = blockIdx.x * 32;
    int mt = row0 >> 7, rbase = row0 & 127;
#pragma unroll
    for (int rr = 0; rr < 4; rr++) {
        int r = warp * 4 + rr;
        const float4* xr = (const float4*)(x + (size_t)(row0 + r) * Kf);
        float mx = 0.f;
        for (int i = lane; i < Kf / 4; i += 32) {
            float4 v = xr[i];
            mx = fmaxf(mx, fmaxf(fmaxf(fabsf(v.x), fabsf(v.y)), fmaxf(fabsf(v.z), fabsf(v.w))));
        }
#pragma unroll
        for (int o = 16; o > 0; o >>= 1) mx = fmaxf(mx, __shfl_xor_sync(0xFFFFFFFFu, mx, o));
        if (lane == 0) {
            float cm = fmaxf(mx, 1e-5f);
            rscale[r] = 127.f / cm;
            rinvs[r] = cm * (1.f / 127.f);
        }
    }
    __syncthreads();
    if (t < 32) ainv[row0 + t] = rinvs[t];
    int r = t >> 3, seg = t & 7;
    int rloc = rbase + r;
    float sc = rscale[r];
    const float* xr = x + (size_t)(row0 + r) * Kf;
    for (int kt = 0; kt < nch; kt++) {
        size_t blob = ((size_t)(mt * nch + kt)) << 14;
        int words[4];
#pragma unroll
        for (int q = 0; q < 4; q++) {
            words[q] = quant_word(*(const float4*)(xr + kt * 128 + seg * 16 + q * 4), sc, -128.f, 127.f);
            s[seg * 4 + q][r] = words[q];
        }
        *(int4*)(xq + blob + rloc * 128 + ((seg ^ (rloc & 7)) << 4)) =
            make_int4(words[0], words[1], words[2], words[3]);
        __syncthreads();
#pragma unroll
        for (int q = 0; q < 4; q++) {
            int kw = q * 8 + warp;
            *(int*)(xqt + blob + kw * 512 + (rbase + lane) * 4) = s[kw][lane];
        }
        __syncthreads();
    }
}

// ======================= rmsnorm + act quant -> hq/hqt blobs =======================
__global__ void rmsnorm_quant(const float* __restrict__ h, const float* __restrict__ lnw,
                              signed char* __restrict__ hq, signed char* __restrict__ hqt,
                              float* __restrict__ hinv) {
    __shared__ float sh[Idim];
    __shared__ float red[256];
    int tid = threadIdx.x;
    int row = blockIdx.x;
    int mt = row >> 7, rloc = row & 127;
    long base = (long)row * Idim;
    float ss = 0.f;
    for (int i = tid; i < Idim; i += 256) {
        float v = h[base + i];
        sh[i] = v;
        ss += v * v;
    }
    red[tid] = ss;
    __syncthreads();
    for (int o = 128; o > 0; o >>= 1) {
        if (tid < o) red[tid] += red[tid + o];
        __syncthreads();
    }
    float rs = rsqrtf(red[0] / (float)Idim + 1e-6f);
    __syncthreads();
    float mx = 0.f;
    for (int i = tid; i < Idim; i += 256) {
        float hn = lnw[i] * sh[i] * rs;
        sh[i] = hn;
        mx = fmaxf(mx, fabsf(hn));
    }
    red[tid] = mx;
    __syncthreads();
    for (int o = 128; o > 0; o >>= 1) {
        if (tid < o) red[tid] = fmaxf(red[tid], red[tid + o]);
        __syncthreads();
    }
    float cm = fmaxf(red[0], 1e-5f);
    float s = 127.f / cm;
    if (tid == 0) hinv[row] = cm * (1.f / 127.f);
    __syncthreads();
    for (int g = tid; g < Idim / 16; g += 256) {
        int kt = g >> 3, c16 = g & 7;
        size_t blob = ((size_t)(mt * NCH_I + kt)) << 14;
        int w[4];
#pragma unroll
        for (int qi = 0; qi < 4; qi++) {
            const float* p = sh + g * 16 + qi * 4;
            w[qi] = quant_word(make_float4(p[0], p[1], p[2], p[3]), s, -128.f, 127.f);
            *(int*)(hqt + blob + (c16 * 4 + qi) * 512 + rloc * 4) = w[qi];
        }
        *(int4*)(hq + blob + rloc * 128 + ((c16 ^ (rloc & 7)) << 4)) =
            make_int4(w[0], w[1], w[2], w[3]);
    }
}

// ======================= hybrid GEMM: 128x64 tile, 2 CTAs/SM, SW-pipelined dp4a =======
template<int NB, int STAGES>
__global__ void __launch_bounds__(256, 2)
gemm_hyb(const signed char* __restrict__ A, const signed char* __restrict__ At,
         const signed char* __restrict__ B0, const signed char* __restrict__ B1,
         float* __restrict__ C, int NC, int Nout,
         const float* __restrict__ rowinv, int iw0, int iw1)
{
    extern __shared__ char smem[];
    char* sp = (char*)(((uintptr_t)smem + 1023u) & ~(uintptr_t)1023u);
    const uint32_t db = smem_u32(sp);
    constexpr uint32_t STAGE_B = (NB == 2) ? 49152u : 40960u;
    const uint32_t mb = db + STAGES * STAGE_B;
    const int tid = threadIdx.x, lane = tid & 31, wid = tid >> 5;
    const int m0 = blockIdx.x * 128, n0 = blockIdx.y * 64;

    if (tid == 0)
        for (int s = 0; s < STAGES; s++) MBAR_INIT(mb + s * 8, 1);
    __syncthreads();

    const size_t blobA = ((size_t)blockIdx.x * NC) << 14;
    const size_t blobB = ((size_t)blockIdx.y * NC) << 13;

    auto issue = [&](int chunk) {
        if (tid != 0) return;
        int st = chunk % STAGES;
        uint32_t bar = mb + st * 8;
        uint32_t base = db + st * STAGE_B;
        MBAR_EXPECT(bar, STAGE_B);
        bulk_g2s(base,          A  + blobA + ((size_t)chunk << 14), 16384, bar);
        bulk_g2s(base + 16384,  At + blobA + ((size_t)chunk << 14), 16384, bar);
        bulk_g2s(base + 32768,  B0 + blobB + ((size_t)chunk << 13), 8192, bar);
        if (NB == 2) bulk_g2s(base + 40960, B1 + blobB + ((size_t)chunk << 13), 8192, bar);
    };

    auto swz = [](int row, int c16) -> uint32_t {
        return (uint32_t)(row * 128 + ((c16 ^ (row & 7)) << 4));
    };

    // MMA-side state (warps 4..7)
    const int wm = wid - 4;
    const int arow = (lane & 7) + ((lane & 8) ? 8 : 0);
    const int acol = (lane >> 4);
    const int brow = (lane & 7) + ((lane & 16) ? 8 : 0);
    const int bcol = ((lane >> 3) & 1);
    int acc[NB][2][4][4];
#pragma unroll
    for (int b = 0; b < NB; b++)
#pragma unroll
        for (int mt = 0; mt < 2; mt++)
#pragma unroll
            for (int n8 = 0; n8 < 4; n8++)
#pragma unroll
                for (int q = 0; q < 4; q++) acc[b][mt][n8][q] = 0;

    // dp4a-side state (warps 0..3)
    const int drow = wid * 32 + ((lane >> 3) << 3);
    const int dcol = (lane & 7) << 2;
    int dac0[8][4], dac1[8][4];
#pragma unroll
    for (int i = 0; i < 8; i++)
#pragma unroll
        for (int j = 0; j < 4; j++) { dac0[i][j] = 0; if (NB == 2) dac1[i][j] = 0; }

    int fill = 0;
    for (; fill < STAGES - 1 && fill < NC; fill++) issue(fill);

    for (int ch = 0; ch < NC; ch++) {
        if (fill < NC) { issue(fill); fill++; }
        int st = ch % STAGES;
        mbar_wait(mb + st * 8, (ch / STAGES) & 1);

        uint32_t sboff = (uint32_t)st * STAGE_B;
        if (wid >= 4) {
            uint32_t abase = db + sboff;
#pragma unroll
            for (int s = 0; s < 4; s++) {
                uint32_t af[2][4];
#pragma unroll
                for (int mt = 0; mt < 2; mt++) {
                    int row = wm * 32 + mt * 16 + arow;
                    LDSM4(af[mt], abase + swz(row, s * 2 + acol));
                }
#pragma unroll
                for (int b = 0; b < NB; b++) {
                    uint32_t bb = abase + 32768u + (uint32_t)b * 8192u;
#pragma unroll
                    for (int nt = 0; nt < 2; nt++) {
                        uint32_t bf[4];
                        int row = nt * 16 + brow;
                        LDSM4(bf, bb + swz(row, s * 2 + bcol));
#pragma unroll
                        for (int mt = 0; mt < 2; mt++) {
                            MMA_S8(acc[b][mt][nt * 2 + 0], af[mt], bf[0], bf[1]);
                            MMA_S8(acc[b][mt][nt * 2 + 1], af[mt], bf[2], bf[3]);
                        }
                    }
                }
            }
        } else {
            // --- software-pipelined dp4a: loads for kk+1 issued before consuming kk ---
            uint32_t at  = db + sboff + 16384u + (uint32_t)(drow * 4);
            uint32_t bt0 = db + sboff + 32768u + 4096u + (uint32_t)(dcol * 4);
            uint32_t bt1 = db + sboff + 40960u + 4096u + (uint32_t)(dcol * 4);
            int4 ca0, ca1, cb0, cb1;
            LDS128(ca0, at); LDS128(ca1, at + 16);
            LDS128(cb0, bt0);
            if (NB == 2) LDS128(cb1, bt1);
#pragma unroll 8
            for (int kk = 0; kk < 32; kk++) {
                int4 na0, na1, nb0, nb1;
                if (kk < 31) {
                    LDS128(na0, at + (kk + 1) * 512);
                    LDS128(na1, at + (kk + 1) * 512 + 16);
                    LDS128(nb0, bt0 + (kk + 1) * 128);
                    if (NB == 2) LDS128(nb1, bt1 + (kk + 1) * 128);
                }
                int a[8] = {ca0.x, ca0.y, ca0.z, ca0.w, ca1.x, ca1.y, ca1.z, ca1.w};
                int b0w[4] = {cb0.x, cb0.y, cb0.z, cb0.w};
#pragma unroll
                for (int i = 0; i < 8; i++)
#pragma unroll
                    for (int j = 0; j < 4; j++)
                        dac0[i][j] = __dp4a(a[i], b0w[j], dac0[i][j]);
                if (NB == 2) {
                    int b1w[4] = {cb1.x, cb1.y, cb1.z, cb1.w};
#pragma unroll
                    for (int i = 0; i < 8; i++)
#pragma unroll
                        for (int j = 0; j < 4; j++)
                            dac1[i][j] = __dp4a(a[i], b1w[j], dac1[i][j]);
                }
                if (kk < 31) {
                    ca0 = na0; ca1 = na1; cb0 = nb0;
                    if (NB == 2) cb1 = nb1;
                }
            }
        }
        __syncthreads();
    }

    // ======== epilogue ========
    float wg0 = g_winv[iw0], wu0 = (NB == 2) ? g_winv[iw1] : 0.f;
    if (wid >= 4) {
#pragma unroll
        for (int mt = 0; mt < 2; mt++) {
            int r = m0 + wm * 32 + mt * 16 + (lane >> 2);
            float ai0 = rowinv[r], ai1 = rowinv[r + 8];
            float* crow0 = C + (size_t)r * Nout;
            float* crow1 = C + (size_t)(r + 8) * Nout;
            if (NB == 2) {
                float sg0 = ai0 * wg0, su0 = ai0 * wu0;
                float sg1 = ai1 * wg0, su1 = ai1 * wu0;
#pragma unroll
                for (int n8 = 0; n8 < 4; n8++) {
                    int c = n0 + n8 * 8 + (lane & 3) * 2;
                    float g00 = (float)acc[0][mt][n8][0] * sg0;
                    float g01 = (float)acc[0][mt][n8][1] * sg0;
                    float g10 = (float)acc[0][mt][n8][2] * sg1;
                    float g11 = (float)acc[0][mt][n8][3] * sg1;
                    float u00 = (float)acc[1][mt][n8][0] * su0;
                    float u01 = (float)acc[1][mt][n8][1] * su0;
                    float u10 = (float)acc[1][mt][n8][2] * su1;
                    float u11 = (float)acc[1][mt][n8][3] * su1;
                    float2 o0, o1;
                    o0.x = (g00 / (1.f + expf(-g00))) * u00;
                    o0.y = (g01 / (1.f + expf(-g01))) * u01;
                    o1.x = (g10 / (1.f + expf(-g10))) * u10;
                    o1.y = (g11 / (1.f + expf(-g11))) * u11;
                    *(float2*)(crow0 + c) = o0;
                    *(float2*)(crow1 + c) = o1;
                }
            } else {
                float s0 = ai0 * wg0, s1 = ai1 * wg0;
#pragma unroll
                for (int n8 = 0; n8 < 4; n8++) {
                    int c = n0 + n8 * 8 + (lane & 3) * 2;
                    float2 o0, o1;
                    o0.x = (float)acc[0][mt][n8][0] * s0;
                    o0.y = (float)acc[0][mt][n8][1] * s0;
                    o1.x = (float)acc[0][mt][n8][2] * s1;
                    o1.y = (float)acc[0][mt][n8][3] * s1;
                    *(float2*)(crow0 + c) = o0;
                    *(float2*)(crow1 + c) = o1;
                }
            }
        }
    } else {
        int cbase = n0 + 32 + dcol;
#pragma unroll
        for (int i = 0; i < 8; i++) {
            int r = m0 + drow + i;
            float ai = rowinv[r];
            float* crow = C + (size_t)r * Nout + cbase;
            if (NB == 2) {
                float sg = ai * wg0, su = ai * wu0;
                float4 o;
                float g0 = (float)dac0[i][0] * sg, u0 = (float)dac1[i][0] * su;
                float g1 = (float)dac0[i][1] * sg, u1 = (float)dac1[i][1] * su;
                float g2 = (float)dac0[i][2] * sg, u2 = (float)dac1[i][2] * su;
                float g3 = (float)dac0[i][3] * sg, u3 = (float)dac1[i][3] * su;
                o.x = (g0 / (1.f + expf(-g0))) * u0;
                o.y = (g1 / (1.f + expf(-g1))) * u1;
                o.z = (g2 / (1.f + expf(-g2))) * u2;
                o.w = (g3 / (1.f + expf(-g3))) * u3;
                *(float4*)crow = o;
            } else {
                float sc = ai * wg0;
                float4 o;
                o.x = (float)dac0[i][0] * sc;
                o.y = (float)dac0[i][1] * sc;
                o.z = (float)dac0[i][2] * sc;
                o.w = (float)dac0[i][3] * sc;
                *(float4*)crow = o;
            }
        }
    }
}

// ======================= launch =======================
extern "C" void kernel_launch(void* const* d_in, const int* in_sizes, int n_in,
                              void* d_out, int out_size) {
    const float* x   = (const float*)d_in[0];
    const float* wg  = (const float*)d_in[1];
    const float* wu  = (const float*)d_in[2];
    const float* wd  = (const float*)d_in[3];
    const float* lnw = (const float*)d_in[4];
    float* out = (float*)d_out;

    signed char *wqg, *wqu, *wqd, *xq, *xqt, *hq, *hqt;
    float *gbuf, *ainv, *hinv;
    cudaGetSymbolAddress((void**)&wqg, g_wqg);
    cudaGetSymbolAddress((void**)&wqu, g_wqu);
    cudaGetSymbolAddress((void**)&wqd, g_wqd);
    cudaGetSymbolAddress((void**)&xq, g_xq);
    cudaGetSymbolAddress((void**)&xqt, g_xqt);
    cudaGetSymbolAddress((void**)&hq, g_hq);
    cudaGetSymbolAddress((void**)&hqt, g_hqt);
    cudaGetSymbolAddress((void**)&gbuf, g_gbuf);
    cudaGetSymbolAddress((void**)&ainv, g_ainv);
    cudaGetSymbolAddress((void**)&hinv, g_hinv);

    const int SMEM2 = 2 * 49152 + 1024 + 64;   // 2 CTAs/SM
    const int SMEM1 = 2 * 40960 + 1024 + 64;   // 2 CTAs/SM
    cudaFuncSetAttribute(gemm_hyb<2, 2>, cudaFuncAttributeMaxDynamicSharedMemorySize, SMEM2);
    cudaFuncSetAttribute(gemm_hyb<1, 2>, cudaFuncAttributeMaxDynamicSharedMemorySize, SMEM1);

    const long NWl = (long)NW;

    absmean_all<<<dim3(2048, 3), 256>>>(wg, wu, wd, NWl);
    quant_weight_all<<<dim3(2752, 3), 256>>>(wg, wu, wd);
    quant_act_t<<<Tdim / 32, 256>>>(x, xq, xqt, ainv, Hdim, NCH_H);
    // ncu slot: fused gate+up hybrid GEMM -> h = silu(g)*u
    gemm_hyb<2, 2><<<dim3(Tdim / 128, Idim / 64), 256, SMEM2>>>(
        xq, xqt, wqg, wqu, gbuf, NCH_H, Idim, ainv, 0, 1);
    rmsnorm_quant<<<Tdim, 256>>>(gbuf, lnw, hq, hqt, hinv);
    gemm_hyb<1, 2><<<dim3(Tdim / 128, Hdim / 64), 256, SMEM1>>>(
        hq, hqt, wqd, wqd, out, NCH_I, Hdim, hinv, 2, 2);
}

// round 15
// speedup vs baseline: 1.5713x; 1.0126x over previous
#include <cuda_runtime.h>
#include <math.h>
#include <stdint.h>

#define Tdim 4096
#define Hdim 4096
#define Idim 11008
#define NW ((size_t)Idim*(size_t)Hdim)
#define NCH_H 32            // Hdim/128
#define NCH_I 86            // Idim/128

// ---- static device scratch ----
// A blobs (16KB per (mtile128, chunk)): kmaj swz rows 0..127; At blobs [kw32][128 words].
// B blobs (8KB per (ntile64, chunk)): [0,4K) cols0..31 kmaj swz; [4K,8K) cols32..63 transposed [kw32][32w]
__device__ __align__(16) signed char g_wqg[NW];
__device__ __align__(16) signed char g_wqu[NW];
__device__ __align__(16) signed char g_wqd[NW];
__device__ __align__(16) signed char g_xq [(size_t)Tdim*Hdim];
__device__ __align__(16) signed char g_xqt[(size_t)Tdim*Hdim];
__device__ __align__(16) signed char g_hq [(size_t)Tdim*Idim];
__device__ __align__(16) signed char g_hqt[(size_t)Tdim*Idim];
__device__ float g_gbuf[(size_t)Tdim*Idim];
__device__ float g_ainv[Tdim];
__device__ float g_hinv[Tdim];
__device__ float g_partial[3][2048];
__device__ float g_wscale[3];
__device__ float g_winv[3];
__device__ unsigned g_cnt = 0;

// ======================= PTX helpers =======================
__device__ __forceinline__ uint32_t smem_u32(const void* p) {
    uint32_t a;
    asm("{ .reg .u64 t; cvta.to.shared.u64 t, %1; cvt.u32.u64 %0, t; }" : "=r"(a) : "l"(p));
    return a;
}
#define MBAR_INIT(a, c) asm volatile("mbarrier.init.shared.b64 [%0], %1;" :: "r"(a), "r"(c) : "memory")
#define MBAR_EXPECT(a, b) asm volatile("mbarrier.arrive.expect_tx.shared.b64 _, [%0], %1;" :: "r"(a), "r"(b) : "memory")
__device__ __forceinline__ void mbar_wait(uint32_t addr, uint32_t parity) {
    asm volatile(
        "{\n\t.reg .pred P;\n\t"
        "LW_%=:\n\t"
        "mbarrier.try_wait.parity.acquire.cta.shared::cta.b64 P, [%0], %1, 0x989680;\n\t"
        "@P bra.uni LD_%=;\n\t"
        "bra.uni LW_%=;\n\t"
        "LD_%=:\n\t}"
        :: "r"(addr), "r"(parity) : "memory");
}
__device__ __forceinline__ void bulk_g2s(uint32_t dst, const void* src, uint32_t bytes, uint32_t mbar) {
    asm volatile("cp.async.bulk.shared::cluster.global.mbarrier::complete_tx::bytes [%0], [%1], %2, [%3];"
        :: "r"(dst), "l"(src), "r"(bytes), "r"(mbar) : "memory");
}
#define LDSM4(r, a) asm volatile( \
    "ldmatrix.sync.aligned.m8n8.x4.shared.b16 {%0,%1,%2,%3}, [%4];" \
    : "=r"((r)[0]), "=r"((r)[1]), "=r"((r)[2]), "=r"((r)[3]) : "r"(a))
#define MMA_S8(d, a, b0, b1) asm volatile( \
    "mma.sync.aligned.m16n8k32.row.col.s32.s8.s8.s32 " \
    "{%0,%1,%2,%3}, {%4,%5,%6,%7}, {%8,%9}, {%0,%1,%2,%3};" \
    : "+r"((d)[0]), "+r"((d)[1]), "+r"((d)[2]), "+r"((d)[3]) \
    : "r"((a)[0]), "r"((a)[1]), "r"((a)[2]), "r"((a)[3]), "r"(b0), "r"(b1))
#define LDS128(v, a) asm volatile("ld.shared.v4.u32 {%0,%1,%2,%3}, [%4];" \
    : "=r"((v).x), "=r"((v).y), "=r"((v).z), "=r"((v).w) : "r"(a))

__device__ __forceinline__ int quant_word(float4 v, float sc, float lo, float hi) {
    int b0 = (int)fminf(hi, fmaxf(lo, rintf(v.x * sc)));
    int b1 = (int)fminf(hi, fmaxf(lo, rintf(v.y * sc)));
    int b2 = (int)fminf(hi, fmaxf(lo, rintf(v.z * sc)));
    int b3 = (int)fminf(hi, fmaxf(lo, rintf(v.w * sc)));
    return (b0 & 0xFF) | ((b1 & 0xFF) << 8) | ((b2 & 0xFF) << 16) | (b3 << 24);
}

// ======================= absmean + finalize (float4 loads) =======================
__global__ void absmean_all(const float* __restrict__ wg, const float* __restrict__ wu,
                            const float* __restrict__ wd, long n) {
    __shared__ float red[256];
    __shared__ double redd[256];
    __shared__ bool amLast;
    int which = blockIdx.y;
    const float* w = which == 0 ? wg : (which == 1 ? wu : wd);
    const float4* w4 = (const float4*)w;
    long n4 = n >> 2;
    float s = 0.f;
    long stride = (long)gridDim.x * blockDim.x;
    for (long i = (long)blockIdx.x * blockDim.x + threadIdx.x; i < n4; i += stride) {
        float4 v = w4[i];
        s += fabsf(v.x) + fabsf(v.y) + fabsf(v.z) + fabsf(v.w);
    }
    red[threadIdx.x] = s;
    __syncthreads();
    for (int o = 128; o > 0; o >>= 1) {
        if (threadIdx.x < o) red[threadIdx.x] += red[threadIdx.x + o];
        __syncthreads();
    }
    if (threadIdx.x == 0) {
        g_partial[which][blockIdx.x] = red[0];
        __threadfence();
        unsigned t = atomicAdd(&g_cnt, 1u);
        amLast = (t == gridDim.x * 3 - 1);
    }
    __syncthreads();
    if (amLast) {
        for (int m = 0; m < 3; m++) {
            double s2 = 0.0;
            for (int i = threadIdx.x; i < 2048; i += 256) s2 += (double)g_partial[m][i];
            redd[threadIdx.x] = s2;
            __syncthreads();
            for (int o = 128; o > 0; o >>= 1) {
                if (threadIdx.x < o) redd[threadIdx.x] += redd[threadIdx.x + o];
                __syncthreads();
            }
            if (threadIdx.x == 0) {
                float mean = (float)(redd[0] / (double)n);
                float cm = fmaxf(mean, 1e-5f);
                g_wscale[m] = 1.f / cm;
                g_winv[m] = cm;
            }
            __syncthreads();
        }
        if (threadIdx.x == 0) g_cnt = 0;
    }
}

// ======================= weight quant -> 8KB B blobs per (ntile64, chunk) ===========
__global__ void quant_weight_all(const float* __restrict__ wg, const float* __restrict__ wu,
                                 const float* __restrict__ wd) {
    __shared__ int s[32][133];
    int which = blockIdx.y;
    const float* w; signed char* outb; int Kf, ktc;
    if (which == 0)      { w = wg; outb = g_wqg; Kf = Hdim; ktc = NCH_H; }
    else if (which == 1) { w = wu; outb = g_wqu; Kf = Hdim; ktc = NCH_H; }
    else                 { w = wd; outb = g_wqd; Kf = Idim; ktc = NCH_I; }
    int bx = blockIdx.x;
    int kc = bx % ktc, nt128 = bx / ktc;
    int kc0 = kc * 128, n0 = nt128 * 128;
    float sw = g_wscale[which];
    int t = threadIdx.x;
    int r = t >> 1, h = t & 1;
    const float* wr = w + (size_t)(n0 + r) * Kf + kc0 + h * 64;
    int words[16];
#pragma unroll
    for (int q = 0; q < 16; q++) {
        words[q] = quant_word(*(const float4*)(wr + q * 4), sw, -1.f, 1.f);
        s[h * 16 + q][r] = words[q];
    }
    if ((r & 63) < 32) {
        int nt64 = nt128 * 2 + (r >> 6);
        int rloc = r & 31;
        signed char* blob = outb + (((size_t)nt64 * ktc + kc) << 13);
#pragma unroll
        for (int qq = 0; qq < 4; qq++) {
            int c16 = h * 4 + qq;
            *(int4*)(blob + rloc * 128 + ((c16 ^ (rloc & 7)) << 4)) =
                make_int4(words[qq*4], words[qq*4+1], words[qq*4+2], words[qq*4+3]);
        }
    }
    __syncthreads();
    int kw = t >> 3, seg = t & 7;
    int nt64 = nt128 * 2 + (seg >> 2);
    int cseg = seg & 3;
    signed char* blob = outb + (((size_t)nt64 * ktc + kc) << 13);
    int srcbase = (seg >> 2) * 64 + 32 + cseg * 8;
    signed char* tp = blob + 4096 + kw * 128 + cseg * 32;
    *(int4*)tp = make_int4(s[kw][srcbase+0], s[kw][srcbase+1], s[kw][srcbase+2], s[kw][srcbase+3]);
    *(int4*)(tp+16) = make_int4(s[kw][srcbase+4], s[kw][srcbase+5], s[kw][srcbase+6], s[kw][srcbase+7]);
}

// ======================= act quant -> A blob (swz) + At blob (transposed) =======================
__global__ void quant_act_t(const float* __restrict__ x, signed char* __restrict__ xq,
                            signed char* __restrict__ xqt, float* __restrict__ ainv,
                            int Kf, int nch) {
    __shared__ float rscale[32];
    __shared__ float rinvs[32];
    __shared__ int s[32][33];
    int t = threadIdx.x, warp = t >> 5, lane = t & 31;
    int row0 = blockIdx.x * 32;
    int mt = row0 >> 7, rbase = row0 & 127;
#pragma unroll
    for (int rr = 0; rr < 4; rr++) {
        int r = warp * 4 + rr;
        const float4* xr = (const float4*)(x + (size_t)(row0 + r) * Kf);
        float mx = 0.f;
        for (int i = lane; i < Kf / 4; i += 32) {
            float4 v = xr[i];
            mx = fmaxf(mx, fmaxf(fmaxf(fabsf(v.x), fabsf(v.y)), fmaxf(fabsf(v.z), fabsf(v.w))));
        }
#pragma unroll
        for (int o = 16; o > 0; o >>= 1) mx = fmaxf(mx, __shfl_xor_sync(0xFFFFFFFFu, mx, o));
        if (lane == 0) {
            float cm = fmaxf(mx, 1e-5f);
            rscale[r] = 127.f / cm;
            rinvs[r] = cm * (1.f / 127.f);
        }
    }
    __syncthreads();
    if (t < 32) ainv[row0 + t] = rinvs[t];
    int r = t >> 3, seg = t & 7;
    int rloc = rbase + r;
    float sc = rscale[r];
    const float* xr = x + (size_t)(row0 + r) * Kf;
    for (int kt = 0; kt < nch; kt++) {
        size_t blob = ((size_t)(mt * nch + kt)) << 14;
        int words[4];
#pragma unroll
        for (int q = 0; q < 4; q++) {
            words[q] = quant_word(*(const float4*)(xr + kt * 128 + seg * 16 + q * 4), sc, -128.f, 127.f);
            s[seg * 4 + q][r] = words[q];
        }
        *(int4*)(xq + blob + rloc * 128 + ((seg ^ (rloc & 7)) << 4)) =
            make_int4(words[0], words[1], words[2], words[3]);
        __syncthreads();
#pragma unroll
        for (int q = 0; q < 4; q++) {
            int kw = q * 8 + warp;
            *(int*)(xqt + blob + kw * 512 + (rbase + lane) * 4) = s[kw][lane];
        }
        __syncthreads();
    }
}

// ======================= rmsnorm + act quant -> hq/hqt blobs =======================
__global__ void rmsnorm_quant(const float* __restrict__ h, const float* __restrict__ lnw,
                              signed char* __restrict__ hq, signed char* __restrict__ hqt,
                              float* __restrict__ hinv) {
    __shared__ float sh[Idim];
    __shared__ float red[256];
    int tid = threadIdx.x;
    int row = blockIdx.x;
    int mt = row >> 7, rloc = row & 127;
    long base = (long)row * Idim;
    float ss = 0.f;
    for (int i = tid; i < Idim; i += 256) {
        float v = h[base + i];
        sh[i] = v;
        ss += v * v;
    }
    red[tid] = ss;
    __syncthreads();
    for (int o = 128; o > 0; o >>= 1) {
        if (tid < o) red[tid] += red[tid + o];
        __syncthreads();
    }
    float rs = rsqrtf(red[0] / (float)Idim + 1e-6f);
    __syncthreads();
    float mx = 0.f;
    for (int i = tid; i < Idim; i += 256) {
        float hn = lnw[i] * sh[i] * rs;
        sh[i] = hn;
        mx = fmaxf(mx, fabsf(hn));
    }
    red[tid] = mx;
    __syncthreads();
    for (int o = 128; o > 0; o >>= 1) {
        if (tid < o) red[tid] = fmaxf(red[tid], red[tid + o]);
        __syncthreads();
    }
    float cm = fmaxf(red[0], 1e-5f);
    float s = 127.f / cm;
    if (tid == 0) hinv[row] = cm * (1.f / 127.f);
    __syncthreads();
    for (int g = tid; g < Idim / 16; g += 256) {
        int kt = g >> 3, c16 = g & 7;
        size_t blob = ((size_t)(mt * NCH_I + kt)) << 14;
        int w[4];
#pragma unroll
        for (int qi = 0; qi < 4; qi++) {
            const float* p = sh + g * 16 + qi * 4;
            w[qi] = quant_word(make_float4(p[0], p[1], p[2], p[3]), s, -128.f, 127.f);
            *(int*)(hqt + blob + (c16 * 4 + qi) * 512 + rloc * 4) = w[qi];
        }
        *(int4*)(hq + blob + rloc * 128 + ((c16 ^ (rloc & 7)) << 4)) =
            make_int4(w[0], w[1], w[2], w[3]);
    }
}

// ======================= hybrid GEMM: 128x64 tile, 2 CTAs/SM, ping-pong dp4a =======
template<int NB, int STAGES>
__global__ void __launch_bounds__(256, 2)
gemm_hyb(const signed char* __restrict__ A, const signed char* __restrict__ At,
         const signed char* __restrict__ B0, const signed char* __restrict__ B1,
         float* __restrict__ C, int NC, int Nout,
         const float* __restrict__ rowinv, int iw0, int iw1)
{
    extern __shared__ char smem[];
    char* sp = (char*)(((uintptr_t)smem + 1023u) & ~(uintptr_t)1023u);
    const uint32_t db = smem_u32(sp);
    constexpr uint32_t STAGE_B = (NB == 2) ? 49152u : 40960u;
    const uint32_t mb = db + STAGES * STAGE_B;
    const int tid = threadIdx.x, lane = tid & 31, wid = tid >> 5;
    const int m0 = blockIdx.x * 128, n0 = blockIdx.y * 64;

    if (tid == 0)
        for (int s = 0; s < STAGES; s++) MBAR_INIT(mb + s * 8, 1);
    __syncthreads();

    const size_t blobA = ((size_t)blockIdx.x * NC) << 14;
    const size_t blobB = ((size_t)blockIdx.y * NC) << 13;

    auto issue = [&](int chunk) {
        if (tid != 0) return;
        int st = chunk % STAGES;
        uint32_t bar = mb + st * 8;
        uint32_t base = db + st * STAGE_B;
        MBAR_EXPECT(bar, STAGE_B);
        bulk_g2s(base,          A  + blobA + ((size_t)chunk << 14), 16384, bar);
        bulk_g2s(base + 16384,  At + blobA + ((size_t)chunk << 14), 16384, bar);
        bulk_g2s(base + 32768,  B0 + blobB + ((size_t)chunk << 13), 8192, bar);
        if (NB == 2) bulk_g2s(base + 40960, B1 + blobB + ((size_t)chunk << 13), 8192, bar);
    };

    auto swz = [](int row, int c16) -> uint32_t {
        return (uint32_t)(row * 128 + ((c16 ^ (row & 7)) << 4));
    };

    // MMA-side state (warps 4..7)
    const int wm = wid - 4;
    const int arow = (lane & 7) + ((lane & 8) ? 8 : 0);
    const int acol = (lane >> 4);
    const int brow = (lane & 7) + ((lane & 16) ? 8 : 0);
    const int bcol = ((lane >> 3) & 1);
    int acc[NB][2][4][4];
#pragma unroll
    for (int b = 0; b < NB; b++)
#pragma unroll
        for (int mt = 0; mt < 2; mt++)
#pragma unroll
            for (int n8 = 0; n8 < 4; n8++)
#pragma unroll
                for (int q = 0; q < 4; q++) acc[b][mt][n8][q] = 0;

    // dp4a-side state (warps 0..3)
    const int drow = wid * 32 + ((lane >> 3) << 3);
    const int dcol = (lane & 7) << 2;
    int dac0[8][4], dac1[8][4];
#pragma unroll
    for (int i = 0; i < 8; i++)
#pragma unroll
        for (int j = 0; j < 4; j++) { dac0[i][j] = 0; if (NB == 2) dac1[i][j] = 0; }

    int fill = 0;
    for (; fill < STAGES - 1 && fill < NC; fill++) issue(fill);

    for (int ch = 0; ch < NC; ch++) {
        if (fill < NC) { issue(fill); fill++; }
        int st = ch % STAGES;
        mbar_wait(mb + st * 8, (ch / STAGES) & 1);

        uint32_t sboff = (uint32_t)st * STAGE_B;
        if (wid >= 4) {
            uint32_t abase = db + sboff;
#pragma unroll
            for (int s = 0; s < 4; s++) {
                uint32_t af[2][4];
#pragma unroll
                for (int mt = 0; mt < 2; mt++) {
                    int row = wm * 32 + mt * 16 + arow;
                    LDSM4(af[mt], abase + swz(row, s * 2 + acol));
                }
#pragma unroll
                for (int b = 0; b < NB; b++) {
                    uint32_t bb = abase + 32768u + (uint32_t)b * 8192u;
#pragma unroll
                    for (int nt = 0; nt < 2; nt++) {
                        uint32_t bf[4];
                        int row = nt * 16 + brow;
                        LDSM4(bf, bb + swz(row, s * 2 + bcol));
#pragma unroll
                        for (int mt = 0; mt < 2; mt++) {
                            MMA_S8(acc[b][mt][nt * 2 + 0], af[mt], bf[0], bf[1]);
                            MMA_S8(acc[b][mt][nt * 2 + 1], af[mt], bf[2], bf[3]);
                        }
                    }
                }
            }
        } else {
            // --- ping-pong dp4a: two-deep register buffers indexed by kk&1 (no copy MOVs) ---
            uint32_t at  = db + sboff + 16384u + (uint32_t)(drow * 4);
            uint32_t bt0 = db + sboff + 32768u + 4096u + (uint32_t)(dcol * 4);
            uint32_t bt1 = db + sboff + 40960u + 4096u + (uint32_t)(dcol * 4);
            int4 a0b[2], a1b[2], b0b[2], b1b[2];
            LDS128(a0b[0], at); LDS128(a1b[0], at + 16);
            LDS128(b0b[0], bt0);
            if (NB == 2) LDS128(b1b[0], bt1);
#pragma unroll 8
            for (int kk = 0; kk < 32; kk++) {
                const int cur = kk & 1, nxt = cur ^ 1;
                if (kk < 31) {
                    LDS128(a0b[nxt], at + (kk + 1) * 512);
                    LDS128(a1b[nxt], at + (kk + 1) * 512 + 16);
                    LDS128(b0b[nxt], bt0 + (kk + 1) * 128);
                    if (NB == 2) LDS128(b1b[nxt], bt1 + (kk + 1) * 128);
                }
                int a[8] = {a0b[cur].x, a0b[cur].y, a0b[cur].z, a0b[cur].w,
                            a1b[cur].x, a1b[cur].y, a1b[cur].z, a1b[cur].w};
                int b0w[4] = {b0b[cur].x, b0b[cur].y, b0b[cur].z, b0b[cur].w};
#pragma unroll
                for (int i = 0; i < 8; i++)
#pragma unroll
                    for (int j = 0; j < 4; j++)
                        dac0[i][j] = __dp4a(a[i], b0w[j], dac0[i][j]);
                if (NB == 2) {
                    int b1w[4] = {b1b[cur].x, b1b[cur].y, b1b[cur].z, b1b[cur].w};
#pragma unroll
                    for (int i = 0; i < 8; i++)
#pragma unroll
                        for (int j = 0; j < 4; j++)
                            dac1[i][j] = __dp4a(a[i], b1w[j], dac1[i][j]);
                }
            }
        }
        __syncthreads();
    }

    // ======== epilogue ========
    float wg0 = g_winv[iw0], wu0 = (NB == 2) ? g_winv[iw1] : 0.f;
    if (wid >= 4) {
#pragma unroll
        for (int mt = 0; mt < 2; mt++) {
            int r = m0 + wm * 32 + mt * 16 + (lane >> 2);
            float ai0 = rowinv[r], ai1 = rowinv[r + 8];
            float* crow0 = C + (size_t)r * Nout;
            float* crow1 = C + (size_t)(r + 8) * Nout;
            if (NB == 2) {
                float sg0 = ai0 * wg0, su0 = ai0 * wu0;
                float sg1 = ai1 * wg0, su1 = ai1 * wu0;
#pragma unroll
                for (int n8 = 0; n8 < 4; n8++) {
                    int c = n0 + n8 * 8 + (lane & 3) * 2;
                    float g00 = (float)acc[0][mt][n8][0] * sg0;
                    float g01 = (float)acc[0][mt][n8][1] * sg0;
                    float g10 = (float)acc[0][mt][n8][2] * sg1;
                    float g11 = (float)acc[0][mt][n8][3] * sg1;
                    float u00 = (float)acc[1][mt][n8][0] * su0;
                    float u01 = (float)acc[1][mt][n8][1] * su0;
                    float u10 = (float)acc[1][mt][n8][2] * su1;
                    float u11 = (float)acc[1][mt][n8][3] * su1;
                    float2 o0, o1;
                    o0.x = (g00 / (1.f + expf(-g00))) * u00;
                    o0.y = (g01 / (1.f + expf(-g01))) * u01;
                    o1.x = (g10 / (1.f + expf(-g10))) * u10;
                    o1.y = (g11 / (1.f + expf(-g11))) * u11;
                    *(float2*)(crow0 + c) = o0;
                    *(float2*)(crow1 + c) = o1;
                }
            } else {
                float s0 = ai0 * wg0, s1 = ai1 * wg0;
#pragma unroll
                for (int n8 = 0; n8 < 4; n8++) {
                    int c = n0 + n8 * 8 + (lane & 3) * 2;
                    float2 o0, o1;
                    o0.x = (float)acc[0][mt][n8][0] * s0;
                    o0.y = (float)acc[0][mt][n8][1] * s0;
                    o1.x = (float)acc[0][mt][n8][2] * s1;
                    o1.y = (float)acc[0][mt][n8][3] * s1;
                    *(float2*)(crow0 + c) = o0;
                    *(float2*)(crow1 + c) = o1;
                }
            }
        }
    } else {
        int cbase = n0 + 32 + dcol;
#pragma unroll
        for (int i = 0; i < 8; i++) {
            int r = m0 + drow + i;
            float ai = rowinv[r];
            float* crow = C + (size_t)r * Nout + cbase;
            if (NB == 2) {
                float sg = ai * wg0, su = ai * wu0;
                float4 o;
                float g0 = (float)dac0[i][0] * sg, u0 = (float)dac1[i][0] * su;
                float g1 = (float)dac0[i][1] * sg, u1 = (float)dac1[i][1] * su;
                float g2 = (float)dac0[i][2] * sg, u2 = (float)dac1[i][2] * su;
                float g3 = (float)dac0[i][3] * sg, u3 = (float)dac1[i][3] * su;
                o.x = (g0 / (1.f + expf(-g0))) * u0;
                o.y = (g1 / (1.f + expf(-g1))) * u1;
                o.z = (g2 / (1.f + expf(-g2))) * u2;
                o.w = (g3 / (1.f + expf(-g3))) * u3;
                *(float4*)crow = o;
            } else {
                float sc = ai * wg0;
                float4 o;
                o.x = (float)dac0[i][0] * sc;
                o.y = (float)dac0[i][1] * sc;
                o.z = (float)dac0[i][2] * sc;
                o.w = (float)dac0[i][3] * sc;
                *(float4*)crow = o;
            }
        }
    }
}

// ======================= launch =======================
extern "C" void kernel_launch(void* const* d_in, const int* in_sizes, int n_in,
                              void* d_out, int out_size) {
    const float* x   = (const float*)d_in[0];
    const float* wg  = (const float*)d_in[1];
    const float* wu  = (const float*)d_in[2];
    const float* wd  = (const float*)d_in[3];
    const float* lnw = (const float*)d_in[4];
    float* out = (float*)d_out;

    signed char *wqg, *wqu, *wqd, *xq, *xqt, *hq, *hqt;
    float *gbuf, *ainv, *hinv;
    cudaGetSymbolAddress((void**)&wqg, g_wqg);
    cudaGetSymbolAddress((void**)&wqu, g_wqu);
    cudaGetSymbolAddress((void**)&wqd, g_wqd);
    cudaGetSymbolAddress((void**)&xq, g_xq);
    cudaGetSymbolAddress((void**)&xqt, g_xqt);
    cudaGetSymbolAddress((void**)&hq, g_hq);
    cudaGetSymbolAddress((void**)&hqt, g_hqt);
    cudaGetSymbolAddress((void**)&gbuf, g_gbuf);
    cudaGetSymbolAddress((void**)&ainv, g_ainv);
    cudaGetSymbolAddress((void**)&hinv, g_hinv);

    const int SMEM2 = 2 * 49152 + 1024 + 64;   // 2 CTAs/SM
    const int SMEM1 = 2 * 40960 + 1024 + 64;   // 2 CTAs/SM
    cudaFuncSetAttribute(gemm_hyb<2, 2>, cudaFuncAttributeMaxDynamicSharedMemorySize, SMEM2);
    cudaFuncSetAttribute(gemm_hyb<1, 2>, cudaFuncAttributeMaxDynamicSharedMemorySize, SMEM1);

    const long NWl = (long)NW;

    absmean_all<<<dim3(2048, 3), 256>>>(wg, wu, wd, NWl);
    quant_weight_all<<<dim3(2752, 3), 256>>>(wg, wu, wd);
    quant_act_t<<<Tdim / 32, 256>>>(x, xq, xqt, ainv, Hdim, NCH_H);
    // ncu slot: fused gate+up hybrid GEMM -> h = silu(g)*u
    gemm_hyb<2, 2><<<dim3(Tdim / 128, Idim / 64), 256, SMEM2>>>(
        xq, xqt, wqg, wqu, gbuf, NCH_H, Idim, ainv, 0, 1);
    rmsnorm_quant<<<Tdim, 256>>>(gbuf, lnw, hq, hqt, hinv);
    gemm_hyb<1, 2><<<dim3(Tdim / 128, Hdim / 64), 256, SMEM1>>>(
        hq, hqt, wqd, wqd, out, NCH_I, Hdim, hinv, 2, 2);
}